// round 4
// baseline (speedup 1.0000x reference)
#include <cuda_runtime.h>
#include <math.h>

#define B_SZ 16
#define D_MODEL 384
#define DEPTH 24
#define D_INNER 768
#define D_STATE 16
#define D_CONV 4
#define DT_RANK 24
#define N_CLASSES 1000
#define L_TOK 196
#define NTOK (B_SZ * L_TOK)            // 3136
#define XPROJ_OUT (DT_RANK + 2 * D_STATE)  // 56

#define SQRT_C 0.70710678118654752f
#define MAX_NORM 1.3435028842544403f   // 0.95/sqrt(0.5)
#define C_CURV 0.5f

// ---------------- scratch (device globals; no allocation allowed) ----------
__device__ float g_patches[NTOK * 768];
__device__ float g_hidden [NTOK * D_MODEL];
__device__ float g_resid  [NTOK * D_MODEL];
__device__ float g_hn     [NTOK * D_MODEL];
__device__ float g_tmp    [NTOK * D_MODEL];
__device__ float g_xz     [NTOK * 2 * D_INNER];
__device__ float g_u      [NTOK * D_INNER];
__device__ float g_dbl    [NTOK * XPROJ_OUT];
__device__ float g_dt     [NTOK * D_INNER];
__device__ float g_y      [NTOK * D_INNER];
__device__ float g_pool   [B_SZ * D_MODEL];

// ---------------- helpers ---------------------------------------------------
__device__ __forceinline__ float blockSum384(float v) {
    __shared__ float sh[12];
    #pragma unroll
    for (int o = 16; o; o >>= 1) v += __shfl_xor_sync(0xffffffffu, v, o);
    int w = threadIdx.x >> 5;
    if ((threadIdx.x & 31) == 0) sh[w] = v;
    __syncthreads();
    float s = 0.f;
    #pragma unroll
    for (int i = 0; i < 12; i++) s += sh[i];
    __syncthreads();
    return s;
}

__device__ __forceinline__ float fsigmoid(float x) { return 1.f / (1.f + __expf(-x)); }

// ---------------- im2col for patch embed ------------------------------------
__global__ void k_im2col(const float* __restrict__ x) {
    int idx = blockIdx.x * blockDim.x + threadIdx.x;
    if (idx >= NTOK * 768) return;
    int col = idx % 768, row = idx / 768;
    int b = row / L_TOK, t = row % L_TOK;
    int ph = t / 14, pw = t % 14;
    int c = col >> 8, rem = col & 255, ii = rem >> 4, jj = rem & 15;
    g_patches[idx] = x[((b * 3 + c) * 224 + ph * 16 + ii) * 224 + pw * 16 + jj];
}

// ---------------- tiled SGEMM: C[M,N] = A[M,K] @ W[N,K]^T (+bias) -----------
// Templated on tile/microtile. 256 threads (16x16). BK=16. A and W staged
// transposed in smem (K-major rows) so inner loop reads are float4 from smem.
template<int BM_, int BN_, int TM_, int TN_>
__global__ __launch_bounds__(256) void k_gemm(
    const float* __restrict__ A, const float* __restrict__ W,
    const float* __restrict__ bias, float* __restrict__ C,
    int M, int N, int K)
{
    constexpr int BK_ = 16;
    __shared__ float As[BK_][BM_ + 4];
    __shared__ float Bs[BK_][BN_ + 4];
    const int tid = threadIdx.x;
    const int tx = tid & 15, ty = tid >> 4;
    const int row0 = blockIdx.y * BM_, col0 = blockIdx.x * BN_;
    float acc[TM_][TN_] = {};

    constexpr int A_F4 = BM_ * BK_ / 4;   // float4 loads for A tile
    constexpr int B_F4 = BN_ * BK_ / 4;

    for (int k0 = 0; k0 < K; k0 += BK_) {
        #pragma unroll
        for (int i = 0; i < A_F4 / 256; i++) {
            int id = tid + i * 256;
            int m = id >> 2, kq = id & 3;
            int gm = row0 + m;
            float4 v = make_float4(0.f, 0.f, 0.f, 0.f);
            if (gm < M) v = *(const float4*)&A[(size_t)gm * K + k0 + kq * 4];
            As[kq * 4 + 0][m] = v.x; As[kq * 4 + 1][m] = v.y;
            As[kq * 4 + 2][m] = v.z; As[kq * 4 + 3][m] = v.w;
        }
        #pragma unroll
        for (int i = 0; i < B_F4 / 256; i++) {
            int id = tid + i * 256;
            int n = id >> 2, kq = id & 3;
            int gn = col0 + n;
            float4 v = make_float4(0.f, 0.f, 0.f, 0.f);
            if (gn < N) v = *(const float4*)&W[(size_t)gn * K + k0 + kq * 4];
            Bs[kq * 4 + 0][n] = v.x; Bs[kq * 4 + 1][n] = v.y;
            Bs[kq * 4 + 2][n] = v.z; Bs[kq * 4 + 3][n] = v.w;
        }
        __syncthreads();
        #pragma unroll
        for (int kk = 0; kk < BK_; kk++) {
            float a[TM_], b[TN_];
            #pragma unroll
            for (int i = 0; i < TM_; i += 4) {
                float4 t = *(const float4*)&As[kk][ty * TM_ + i];
                a[i] = t.x; a[i + 1] = t.y; a[i + 2] = t.z; a[i + 3] = t.w;
            }
            #pragma unroll
            for (int j = 0; j < TN_; j += 4) {
                float4 t = *(const float4*)&Bs[kk][tx * TN_ + j];
                b[j] = t.x; b[j + 1] = t.y; b[j + 2] = t.z; b[j + 3] = t.w;
            }
            #pragma unroll
            for (int i = 0; i < TM_; i++)
                #pragma unroll
                for (int j = 0; j < TN_; j++)
                    acc[i][j] += a[i] * b[j];
        }
        __syncthreads();
    }

    #pragma unroll
    for (int i = 0; i < TM_; i++) {
        int gm = row0 + ty * TM_ + i;
        if (gm >= M) continue;
        #pragma unroll
        for (int j = 0; j < TN_; j++) {
            int gn = col0 + tx * TN_ + j;
            if (gn >= N) continue;
            float v = acc[i][j];
            if (bias) v += bias[gn];
            C[(size_t)gm * N + gn] = v;
        }
    }
}

// ---------------- row-wise hyperbolic kernels (384 threads per row) ---------
__global__ void k_expmap_rows(const float* __restrict__ in, float* __restrict__ out) {
    int row = blockIdx.x, e = threadIdx.x;
    float x = in[row * D_MODEL + e];
    float s2 = blockSum384(x * x);
    float n = sqrtf(s2 + 1e-15f);
    n = fminf(fmaxf(n, 1e-8f), 5.0f);
    float coef = tanhf(SQRT_C * n) / (SQRT_C * n);
    float rn = sqrtf(coef * coef * s2 + 1e-15f);
    float scale = (rn > MAX_NORM) ? (MAX_NORM / rn) : 1.f;
    out[row * D_MODEL + e] = coef * x * scale;
}

__global__ void k_logmap_rows(const float* __restrict__ in, float* __restrict__ out) {
    int row = blockIdx.x, e = threadIdx.x;
    float x = in[row * D_MODEL + e];
    float s2 = blockSum384(x * x);
    float n = sqrtf(s2 + 1e-15f);
    n = fminf(fmaxf(n, 1e-8f), MAX_NORM);
    float coef = atanhf(fminf(SQRT_C * n, 0.95f)) / (SQRT_C * n);
    out[row * D_MODEL + e] = coef * x;
}

// mobius_add(mobius_matvec(hyp_w, h), hyp_b); mx precomputed by GEMM.
__global__ void k_mobius(const float* __restrict__ h, const float* __restrict__ mx,
                         const float* __restrict__ hb, float* __restrict__ out) {
    int row = blockIdx.x, e = threadIdx.x;
    float hv = h[row * D_MODEL + e];
    float mv = mx[row * D_MODEL + e];
    float bv = hb[e];
    float sh2  = blockSum384(hv * hv);
    float smx2 = blockSum384(mv * mv);
    float xn  = fmaxf(sqrtf(sh2 + 1e-15f), 1e-8f);
    float mxn = fmaxf(sqrtf(smx2 + 1e-15f), 1e-8f);
    float tt = tanhf(mxn / xn * atanhf(fminf(SQRT_C * xn, 1.f - 1e-5f)));
    float c1 = tt / (mxn * SQRT_C);
    float res = c1 * mv;
    float xy = blockSum384(res * bv);
    float y2 = blockSum384(bv * bv);
    float x2 = c1 * c1 * smx2;
    float alpha = 1.f + 2.f * C_CURV * xy + C_CURV * y2;
    float beta_ = 1.f - C_CURV * x2;
    float den = fmaxf(1.f + 2.f * C_CURV * xy + C_CURV * C_CURV * x2 * y2, 1e-15f);
    out[row * D_MODEL + e] = (alpha * res + beta_ * bv) / den;
}

// Fused: r = (doAdd ? resid + hidden : hidden); resid = r; hn = hyp_ln(r).
__global__ void k_resid_hyp_ln(const float* __restrict__ hidden,
                               float* __restrict__ resid,
                               const float* __restrict__ gamma,
                               const float* __restrict__ beta,
                               float* __restrict__ out, int doAdd) {
    int row = blockIdx.x, e = threadIdx.x;
    float x = hidden[row * D_MODEL + e];
    if (doAdd) x += resid[row * D_MODEL + e];
    resid[row * D_MODEL + e] = x;
    float s2 = blockSum384(x * x);
    float n = sqrtf(s2 + 1e-15f);
    n = fminf(fmaxf(n, 1e-8f), MAX_NORM);
    float coef = atanhf(fminf(SQRT_C * n, 0.95f)) / (SQRT_C * n);
    float t = coef * x;
    float mean = blockSum384(t) * (1.f / D_MODEL);
    float dv = t - mean;
    float var = blockSum384(dv * dv) * (1.f / (D_MODEL - 1));
    float u = dv / (sqrtf(var) + 1e-5f) * gamma[e] + beta[e];
    float su2 = blockSum384(u * u);
    float nu = sqrtf(su2 + 1e-15f);
    nu = fminf(fmaxf(nu, 1e-8f), 5.0f);
    float ec = tanhf(SQRT_C * nu) / (SQRT_C * nu);
    float rn = sqrtf(ec * ec * su2 + 1e-15f);
    float scale = (rn > MAX_NORM) ? (MAX_NORM / rn) : 1.f;
    out[row * D_MODEL + e] = ec * u * scale;
}

// expmap0(logmap0(h) + pos_embed)
__global__ void k_posemb(const float* __restrict__ in, const float* __restrict__ pos,
                         float* __restrict__ out) {
    int row = blockIdx.x, e = threadIdx.x;
    int t = row % L_TOK;
    float x = in[row * D_MODEL + e];
    float s2 = blockSum384(x * x);
    float n = sqrtf(s2 + 1e-15f);
    n = fminf(fmaxf(n, 1e-8f), MAX_NORM);
    float coef = atanhf(fminf(SQRT_C * n, 0.95f)) / (SQRT_C * n);
    float u = coef * x + pos[t * D_MODEL + e];
    float su2 = blockSum384(u * u);
    float nu = sqrtf(su2 + 1e-15f);
    nu = fminf(fmaxf(nu, 1e-8f), 5.0f);
    float ec = tanhf(SQRT_C * nu) / (SQRT_C * nu);
    float rn = sqrtf(ec * ec * su2 + 1e-15f);
    float scale = (rn > MAX_NORM) ? (MAX_NORM / rn) : 1.f;
    out[row * D_MODEL + e] = ec * u * scale;
}

// ---------------- depthwise causal conv + silu ------------------------------
__global__ void k_conv_silu(const float* __restrict__ xz, const float* __restrict__ cw,
                            const float* __restrict__ cb, float* __restrict__ u) {
    int idx = blockIdx.x * blockDim.x + threadIdx.x;
    if (idx >= NTOK * D_INNER) return;
    int d = idx % D_INNER, bt = idx / D_INNER;
    int b = bt / L_TOK, l = bt % L_TOK;
    float acc = cb[d];
    #pragma unroll
    for (int k = 0; k < D_CONV; k++) {
        int l2 = l + k - (D_CONV - 1);
        if (l2 >= 0) acc += cw[d * D_CONV + k] * xz[(b * L_TOK + l2) * (2 * D_INNER) + d];
    }
    u[idx] = acc * fsigmoid(acc);
}

// ---------------- dt projection + softplus ----------------------------------
__global__ void k_dtproj(const float* __restrict__ dbl, const float* __restrict__ dtw,
                         const float* __restrict__ dtb, float* __restrict__ dt) {
    int idx = blockIdx.x * blockDim.x + threadIdx.x;
    if (idx >= NTOK * D_INNER) return;
    int d = idx % D_INNER, bt = idx / D_INNER;
    float acc = dtb[d];
    #pragma unroll
    for (int r = 0; r < DT_RANK; r++)
        acc += dbl[bt * XPROJ_OUT + r] * dtw[d * DT_RANK + r];
    dt[idx] = (acc > 20.f) ? acc : log1pf(__expf(acc));
}

// ---------------- selective scan (+ Dp*u, * silu(z)) ------------------------
__global__ void k_scan(const float* __restrict__ dt, const float* __restrict__ u,
                       const float* __restrict__ dbl, const float* __restrict__ xz,
                       const float* __restrict__ A_log, const float* __restrict__ Dp,
                       float* __restrict__ y) {
    int gid = blockIdx.x * blockDim.x + threadIdx.x;
    int grp = gid >> 4, s = gid & 15;
    if (grp >= B_SZ * D_INNER) return;
    int b = grp / D_INNER, d = grp % D_INNER;
    float a = -expf(A_log[d * D_STATE + s]);
    float Dv = Dp[d];
    float h = 0.f;
    int base0 = b * L_TOK;
    for (int t = 0; t < L_TOK; t++) {
        int bt = base0 + t;
        float dtv = dt[bt * D_INNER + d];
        float uv  = u[bt * D_INNER + d];
        float Bv  = dbl[bt * XPROJ_OUT + DT_RANK + s];
        float Cv  = dbl[bt * XPROJ_OUT + DT_RANK + D_STATE + s];
        h = __expf(dtv * a) * h + dtv * Bv * uv;
        float p = h * Cv;
        p += __shfl_down_sync(0xffffffffu, p, 8, 16);
        p += __shfl_down_sync(0xffffffffu, p, 4, 16);
        p += __shfl_down_sync(0xffffffffu, p, 2, 16);
        p += __shfl_down_sync(0xffffffffu, p, 1, 16);
        if (s == 0) {
            float zv = xz[bt * (2 * D_INNER) + D_INNER + d];
            float yy = p + Dv * uv;
            yy *= zv * fsigmoid(zv);
            y[bt * D_INNER + d] = yy;
        }
    }
}

// ---------------- mean pool over tokens -------------------------------------
__global__ void k_pool(const float* __restrict__ in, float* __restrict__ out) {
    int b = blockIdx.x, e = threadIdx.x;
    float s = 0.f;
    for (int t = 0; t < L_TOK; t++) s += in[(b * L_TOK + t) * D_MODEL + e];
    out[b * D_MODEL + e] = s * (1.f / L_TOK);
}

// ---------------- hyperbolic distance classifier ----------------------------
__global__ void k_classifier(const float* __restrict__ pooled,
                             const float* __restrict__ protos,
                             float* __restrict__ out) {
    int warp = (blockIdx.x * blockDim.x + threadIdx.x) >> 5;
    int lane = threadIdx.x & 31;
    if (warp >= B_SZ * N_CLASSES) return;
    int b = warp / N_CLASSES, c = warp % N_CLASSES;
    float s_ab = 0.f, s_aa = 0.f, s_bb = 0.f;
    for (int e = lane; e < D_MODEL; e += 32) {
        float pa = pooled[b * D_MODEL + e];
        float pr = protos[c * D_MODEL + e];
        s_ab += pa * pr; s_aa += pa * pa; s_bb += pr * pr;
    }
    #pragma unroll
    for (int o = 16; o; o >>= 1) {
        s_ab += __shfl_down_sync(0xffffffffu, s_ab, o);
        s_aa += __shfl_down_sync(0xffffffffu, s_aa, o);
        s_bb += __shfl_down_sync(0xffffffffu, s_bb, o);
    }
    if (lane == 0) {
        float xy = -s_ab;          // a = -pooled
        float x2 = s_aa, y2 = s_bb;
        float alpha = 1.f + 2.f * C_CURV * xy + C_CURV * y2;
        float beta_ = 1.f - C_CURV * x2;
        float num2 = alpha * alpha * x2 + 2.f * alpha * beta_ * xy + beta_ * beta_ * y2;
        float den = fmaxf(1.f + 2.f * C_CURV * xy + C_CURV * C_CURV * x2 * y2, 1e-15f);
        float nrm = sqrtf(fmaxf(num2, 0.f) / (den * den) + 1e-15f);
        float dn = fminf(SQRT_C * nrm, 1.f - 1e-5f);
        out[b * N_CLASSES + c] = -(2.f / SQRT_C) * atanhf(dn);
    }
}

// ---------------- host orchestration ----------------------------------------
static void gemm_big(const float* A, const float* W, const float* bias, float* C,
                     int M, int N, int K) {
    // BM=128, BN=64, 8x4 microtile
    dim3 grid((N + 63) / 64, (M + 127) / 128);
    k_gemm<128, 64, 8, 4><<<grid, 256>>>(A, W, bias, C, M, N, K);
}
static void gemm_small(const float* A, const float* W, const float* bias, float* C,
                       int M, int N, int K) {
    // BM=64, BN=64, 4x4 microtile (for narrow-N x_proj)
    dim3 grid((N + 63) / 64, (M + 63) / 64);
    k_gemm<64, 64, 4, 4><<<grid, 256>>>(A, W, bias, C, M, N, K);
}

extern "C" void kernel_launch(void* const* d_in, const int* in_sizes, int n_in,
                              void* d_out, int out_size) {
    const float* x        = (const float*)d_in[0];
    const float* patch_w  = (const float*)d_in[1];
    const float* patch_b  = (const float*)d_in[2];
    const float* hyp_w    = (const float*)d_in[3];
    const float* hyp_b    = (const float*)d_in[4];
    const float* pe_gamma = (const float*)d_in[5];
    const float* pe_beta  = (const float*)d_in[6];
    const float* pos_emb  = (const float*)d_in[7];
    const float* in_proj  = (const float*)d_in[8];
    const float* conv_w   = (const float*)d_in[9];
    const float* conv_b   = (const float*)d_in[10];
    const float* x_proj   = (const float*)d_in[11];
    const float* dt_w     = (const float*)d_in[12];
    const float* dt_b     = (const float*)d_in[13];
    const float* A_log    = (const float*)d_in[14];
    const float* Dp       = (const float*)d_in[15];
    const float* out_proj = (const float*)d_in[16];
    const float* gamma    = (const float*)d_in[17];
    const float* beta     = (const float*)d_in[18];
    const float* gamma_f  = (const float*)d_in[19];
    const float* beta_f   = (const float*)d_in[20];
    const float* protos   = (const float*)d_in[21];
    float* out = (float*)d_out;

    float *patches, *hidden, *resid, *hn, *tmp, *xz, *u, *dbl, *dtb_, *yb, *pool;
    cudaGetSymbolAddress((void**)&patches, g_patches);
    cudaGetSymbolAddress((void**)&hidden,  g_hidden);
    cudaGetSymbolAddress((void**)&resid,   g_resid);
    cudaGetSymbolAddress((void**)&hn,      g_hn);
    cudaGetSymbolAddress((void**)&tmp,     g_tmp);
    cudaGetSymbolAddress((void**)&xz,      g_xz);
    cudaGetSymbolAddress((void**)&u,       g_u);
    cudaGetSymbolAddress((void**)&dbl,     g_dbl);
    cudaGetSymbolAddress((void**)&dtb_,    g_dt);
    cudaGetSymbolAddress((void**)&yb,      g_y);
    cudaGetSymbolAddress((void**)&pool,    g_pool);

    // patch embed -> tokens
    k_im2col<<<(NTOK * 768 + 255) / 256, 256>>>(x);
    gemm_big(patches, patch_w, patch_b, hidden, NTOK, D_MODEL, 768);
    // hyperbolic embedding
    k_expmap_rows<<<NTOK, D_MODEL>>>(hidden, hidden);
    gemm_big(hidden, hyp_w, nullptr, tmp, NTOK, D_MODEL, D_MODEL);
    k_mobius<<<NTOK, D_MODEL>>>(hidden, tmp, hyp_b, hidden);
    k_resid_hyp_ln<<<NTOK, D_MODEL>>>(hidden, tmp, pe_gamma, pe_beta, hidden, 0);
    k_posemb<<<NTOK, D_MODEL>>>(hidden, pos_emb, hidden);

    for (int i = 0; i < DEPTH; i++) {
        k_resid_hyp_ln<<<NTOK, D_MODEL>>>(hidden, resid,
                                          gamma + i * D_MODEL, beta + i * D_MODEL,
                                          hn, i > 0);
        gemm_big(hn, in_proj + (size_t)i * 2 * D_INNER * D_MODEL, nullptr, xz,
                 NTOK, 2 * D_INNER, D_MODEL);
        k_conv_silu<<<(NTOK * D_INNER + 255) / 256, 256>>>(
            xz, conv_w + i * D_INNER * D_CONV, conv_b + i * D_INNER, u);
        gemm_small(u, x_proj + (size_t)i * XPROJ_OUT * D_INNER, nullptr, dbl,
                   NTOK, XPROJ_OUT, D_INNER);
        k_dtproj<<<(NTOK * D_INNER + 255) / 256, 256>>>(
            dbl, dt_w + (size_t)i * D_INNER * DT_RANK, dt_b + i * D_INNER, dtb_);
        k_scan<<<(B_SZ * D_INNER * 16 + 255) / 256, 256>>>(
            dtb_, u, dbl, xz, A_log + (size_t)i * D_INNER * D_STATE, Dp + i * D_INNER, yb);
        gemm_big(yb, out_proj + (size_t)i * D_MODEL * D_INNER, nullptr, hidden,
                 NTOK, D_MODEL, D_INNER);
    }

    // final residual + LN + pool + classify
    k_resid_hyp_ln<<<NTOK, D_MODEL>>>(hidden, resid, gamma_f, beta_f, hn, 1);
    k_logmap_rows<<<NTOK, D_MODEL>>>(hn, tmp);
    k_pool<<<B_SZ, D_MODEL>>>(tmp, pool);
    k_expmap_rows<<<B_SZ, D_MODEL>>>(pool, pool);
    k_classifier<<<(B_SZ * N_CLASSES * 32 + 255) / 256, 256>>>(pool, protos, out);
}

// round 5
// speedup vs baseline: 1.2044x; 1.2044x over previous
#include <cuda_runtime.h>
#include <math.h>
#include <mma.h>

using namespace nvcuda;

#define B_SZ 16
#define D_MODEL 384
#define DEPTH 24
#define D_INNER 768
#define D_STATE 16
#define D_CONV 4
#define DT_RANK 24
#define N_CLASSES 1000
#define L_TOK 196
#define NTOK (B_SZ * L_TOK)            // 3136
#define XPROJ_OUT (DT_RANK + 2 * D_STATE)  // 56

#define SQRT_C 0.70710678118654752f
#define MAX_NORM 1.3435028842544403f   // 0.95/sqrt(0.5)
#define C_CURV 0.5f

// ---------------- scratch (device globals; no allocation allowed) ----------
__device__ float g_patches[NTOK * 768];
__device__ float g_hidden [NTOK * D_MODEL];
__device__ float g_resid  [NTOK * D_MODEL];
__device__ float g_hn     [NTOK * D_MODEL];
__device__ float g_tmp    [NTOK * D_MODEL];
__device__ float g_xz     [NTOK * 2 * D_INNER];
__device__ float g_u      [NTOK * D_INNER];
__device__ float g_dbl    [NTOK * XPROJ_OUT];
__device__ float g_dt     [NTOK * D_INNER];
__device__ float g_y      [NTOK * D_INNER];
__device__ float g_pool   [B_SZ * D_MODEL];

// ---------------- helpers ---------------------------------------------------
__device__ __forceinline__ float warpSum(float v) {
    #pragma unroll
    for (int o = 16; o; o >>= 1) v += __shfl_xor_sync(0xffffffffu, v, o);
    return v;
}
__device__ __forceinline__ float fsigmoid(float x) { return 1.f / (1.f + __expf(-x)); }

// ---------------- im2col for patch embed ------------------------------------
__global__ void k_im2col(const float* __restrict__ x) {
    int idx = blockIdx.x * blockDim.x + threadIdx.x;
    if (idx >= NTOK * 768) return;
    int col = idx % 768, row = idx / 768;
    int b = row / L_TOK, t = row % L_TOK;
    int ph = t / 14, pw = t % 14;
    int c = col >> 8, rem = col & 255, ii = rem >> 4, jj = rem & 15;
    g_patches[idx] = x[((b * 3 + c) * 224 + ph * 16 + ii) * 224 + pw * 16 + jj];
}

// ---------------- tf32 tensor-core GEMM: C = A[M,K] @ W[N,K]^T (+bias) ------
// BM=128, BN=64, BK=16. 256 threads = 8 warps in 4(m) x 2(n), warp tile 32x32.
// wmma m16n16k8 tf32. Smem-staged epilogue handles bias and ragged N.
#define GLDA 28          // padded lds for A tile rows (mult of 4)
#define GLDB 28
#define GLDC 68
template<bool HAS_BIAS>
__global__ __launch_bounds__(256) void k_gemm_tf32(
    const float* __restrict__ A, const float* __restrict__ W,
    const float* __restrict__ bias, float* __restrict__ C,
    int M, int N, int K)
{
    constexpr int BM = 128, BN = 64, BK = 16;
    __shared__ float smem[BM * GLDC];          // 8704 floats; aliased
    float* As = smem;                          // BM x GLDA
    float* Bs = smem + BM * GLDA;              // BN x GLDB

    const int tid = threadIdx.x;
    const int warp = tid >> 5;
    const int wm = warp >> 1;                  // 0..3
    const int wn = warp & 1;                   // 0..1
    const int row0 = blockIdx.y * BM, col0 = blockIdx.x * BN;

    wmma::fragment<wmma::accumulator, 16, 16, 8, float> acc[2][2];
    #pragma unroll
    for (int i = 0; i < 2; i++)
        #pragma unroll
        for (int j = 0; j < 2; j++) wmma::fill_fragment(acc[i][j], 0.f);

    // A loader: 2048 floats = 256 thr * 2 float4. r = tid>>1, c8 = (tid&1)*8
    const int ar = tid >> 1, ac8 = (tid & 1) * 8;
    // B loader: 1024 floats = 256 thr * 1 float4. n = tid>>2, kq = (tid&3)*4
    const int bn_ = tid >> 2, bk4 = (tid & 3) * 4;

    for (int k0 = 0; k0 < K; k0 += BK) {
        {
            int gm = row0 + ar;
            float4 v0 = make_float4(0.f,0.f,0.f,0.f), v1 = v0;
            if (gm < M) {
                const float* p = &A[(size_t)gm * K + k0 + ac8];
                v0 = *(const float4*)p; v1 = *(const float4*)(p + 4);
            }
            float* d = &As[ar * GLDA + ac8];
            d[0]=wmma::__float_to_tf32(v0.x); d[1]=wmma::__float_to_tf32(v0.y);
            d[2]=wmma::__float_to_tf32(v0.z); d[3]=wmma::__float_to_tf32(v0.w);
            d[4]=wmma::__float_to_tf32(v1.x); d[5]=wmma::__float_to_tf32(v1.y);
            d[6]=wmma::__float_to_tf32(v1.z); d[7]=wmma::__float_to_tf32(v1.w);
        }
        {
            int gn = col0 + bn_;
            float4 v = make_float4(0.f,0.f,0.f,0.f);
            if (gn < N) v = *(const float4*)&W[(size_t)gn * K + k0 + bk4];
            float* d = &Bs[bn_ * GLDB + bk4];
            d[0]=wmma::__float_to_tf32(v.x); d[1]=wmma::__float_to_tf32(v.y);
            d[2]=wmma::__float_to_tf32(v.z); d[3]=wmma::__float_to_tf32(v.w);
        }
        __syncthreads();
        #pragma unroll
        for (int kk = 0; kk < BK; kk += 8) {
            wmma::fragment<wmma::matrix_a, 16, 16, 8, wmma::precision::tf32, wmma::row_major> a[2];
            wmma::fragment<wmma::matrix_b, 16, 16, 8, wmma::precision::tf32, wmma::col_major> b[2];
            #pragma unroll
            for (int i = 0; i < 2; i++)
                wmma::load_matrix_sync(a[i], &As[(wm * 32 + i * 16) * GLDA + kk], GLDA);
            #pragma unroll
            for (int j = 0; j < 2; j++)
                wmma::load_matrix_sync(b[j], &Bs[(wn * 32 + j * 16) * GLDB + kk], GLDB);
            #pragma unroll
            for (int i = 0; i < 2; i++)
                #pragma unroll
                for (int j = 0; j < 2; j++)
                    wmma::mma_sync(acc[i][j], a[i], b[j], acc[i][j]);
        }
        __syncthreads();
    }

    // epilogue via smem (handles bias + ragged M/N)
    #pragma unroll
    for (int i = 0; i < 2; i++)
        #pragma unroll
        for (int j = 0; j < 2; j++)
            wmma::store_matrix_sync(&smem[(wm * 32 + i * 16) * GLDC + wn * 32 + j * 16],
                                    acc[i][j], GLDC, wmma::mem_row_major);
    __syncthreads();
    for (int idx = tid; idx < BM * BN; idx += 256) {
        int m = idx >> 6, n = idx & 63;
        int gm = row0 + m, gn = col0 + n;
        if (gm < M && gn < N) {
            float v = smem[m * GLDC + n];
            if (HAS_BIAS) v += bias[gn];
            C[(size_t)gm * N + gn] = v;
        }
    }
}

// ---------------- warp-per-row hyperbolic kernels ---------------------------
// 8 warps/block, one row (384 elems = 12/lane) per warp, shfl-only reductions.
#define ROWS_PER_BLK 8

__global__ void k_expmap_rows(const float* __restrict__ in, float* __restrict__ out,
                              int nrows) {
    int row = blockIdx.x * ROWS_PER_BLK + (threadIdx.x >> 5);
    if (row >= nrows) return;
    int lane = threadIdx.x & 31;
    float v[12]; float s2 = 0.f;
    #pragma unroll
    for (int j = 0; j < 12; j++) { v[j] = in[row * D_MODEL + lane + j * 32]; s2 += v[j] * v[j]; }
    s2 = warpSum(s2);
    float n = sqrtf(s2 + 1e-15f);
    n = fminf(fmaxf(n, 1e-8f), 5.0f);
    float coef = tanhf(SQRT_C * n) / (SQRT_C * n);
    float rn = sqrtf(coef * coef * s2 + 1e-15f);
    float scale = (rn > MAX_NORM) ? (MAX_NORM / rn) : 1.f;
    #pragma unroll
    for (int j = 0; j < 12; j++) out[row * D_MODEL + lane + j * 32] = coef * v[j] * scale;
}

__global__ void k_logmap_rows(const float* __restrict__ in, float* __restrict__ out,
                              int nrows) {
    int row = blockIdx.x * ROWS_PER_BLK + (threadIdx.x >> 5);
    if (row >= nrows) return;
    int lane = threadIdx.x & 31;
    float v[12]; float s2 = 0.f;
    #pragma unroll
    for (int j = 0; j < 12; j++) { v[j] = in[row * D_MODEL + lane + j * 32]; s2 += v[j] * v[j]; }
    s2 = warpSum(s2);
    float n = sqrtf(s2 + 1e-15f);
    n = fminf(fmaxf(n, 1e-8f), MAX_NORM);
    float coef = atanhf(fminf(SQRT_C * n, 0.95f)) / (SQRT_C * n);
    #pragma unroll
    for (int j = 0; j < 12; j++) out[row * D_MODEL + lane + j * 32] = coef * v[j];
}

__global__ void k_mobius(const float* __restrict__ h, const float* __restrict__ mx,
                         const float* __restrict__ hb, float* __restrict__ out) {
    int row = blockIdx.x * ROWS_PER_BLK + (threadIdx.x >> 5);
    if (row >= NTOK) return;
    int lane = threadIdx.x & 31;
    float hv[12], mv[12], bv[12];
    float sh2 = 0.f, smx2 = 0.f, y2 = 0.f;
    #pragma unroll
    for (int j = 0; j < 12; j++) {
        int e = lane + j * 32;
        hv[j] = h[row * D_MODEL + e]; mv[j] = mx[row * D_MODEL + e]; bv[j] = hb[e];
        sh2 += hv[j] * hv[j]; smx2 += mv[j] * mv[j]; y2 += bv[j] * bv[j];
    }
    sh2 = warpSum(sh2); smx2 = warpSum(smx2); y2 = warpSum(y2);
    float xn  = fmaxf(sqrtf(sh2 + 1e-15f), 1e-8f);
    float mxn = fmaxf(sqrtf(smx2 + 1e-15f), 1e-8f);
    float tt = tanhf(mxn / xn * atanhf(fminf(SQRT_C * xn, 1.f - 1e-5f)));
    float c1 = tt / (mxn * SQRT_C);
    float xy = 0.f;
    #pragma unroll
    for (int j = 0; j < 12; j++) xy += c1 * mv[j] * bv[j];
    xy = warpSum(xy);
    float x2 = c1 * c1 * smx2;
    float alpha = 1.f + 2.f * C_CURV * xy + C_CURV * y2;
    float beta_ = 1.f - C_CURV * x2;
    float den = fmaxf(1.f + 2.f * C_CURV * xy + C_CURV * C_CURV * x2 * y2, 1e-15f);
    float rden = 1.f / den;
    #pragma unroll
    for (int j = 0; j < 12; j++)
        out[row * D_MODEL + lane + j * 32] = (alpha * c1 * mv[j] + beta_ * bv[j]) * rden;
}

// Fused: r = (doAdd ? resid + hidden : hidden); resid = r; out = hyp_ln(r).
__global__ void k_resid_hyp_ln(const float* __restrict__ hidden,
                               float* __restrict__ resid,
                               const float* __restrict__ gamma,
                               const float* __restrict__ beta,
                               float* __restrict__ out, int doAdd) {
    int row = blockIdx.x * ROWS_PER_BLK + (threadIdx.x >> 5);
    if (row >= NTOK) return;
    int lane = threadIdx.x & 31;
    float v[12]; float s2 = 0.f;
    #pragma unroll
    for (int j = 0; j < 12; j++) {
        int e = lane + j * 32;
        float x = hidden[row * D_MODEL + e];
        if (doAdd) x += resid[row * D_MODEL + e];
        resid[row * D_MODEL + e] = x;
        v[j] = x; s2 += x * x;
    }
    s2 = warpSum(s2);
    float n = sqrtf(s2 + 1e-15f);
    n = fminf(fmaxf(n, 1e-8f), MAX_NORM);
    float coef = atanhf(fminf(SQRT_C * n, 0.95f)) / (SQRT_C * n);
    float mean = 0.f;
    #pragma unroll
    for (int j = 0; j < 12; j++) { v[j] *= coef; mean += v[j]; }
    mean = warpSum(mean) * (1.f / D_MODEL);
    float var = 0.f;
    #pragma unroll
    for (int j = 0; j < 12; j++) { v[j] -= mean; var += v[j] * v[j]; }
    var = warpSum(var) * (1.f / (D_MODEL - 1));
    float rstd = 1.f / (sqrtf(var) + 1e-5f);
    float su2 = 0.f;
    #pragma unroll
    for (int j = 0; j < 12; j++) {
        int e = lane + j * 32;
        v[j] = v[j] * rstd * gamma[e] + beta[e];
        su2 += v[j] * v[j];
    }
    su2 = warpSum(su2);
    float nu = sqrtf(su2 + 1e-15f);
    nu = fminf(fmaxf(nu, 1e-8f), 5.0f);
    float ec = tanhf(SQRT_C * nu) / (SQRT_C * nu);
    float rn = sqrtf(ec * ec * su2 + 1e-15f);
    float scale = (rn > MAX_NORM) ? (MAX_NORM / rn) : 1.f;
    #pragma unroll
    for (int j = 0; j < 12; j++) out[row * D_MODEL + lane + j * 32] = ec * v[j] * scale;
}

// expmap0(logmap0(h) + pos_embed)
__global__ void k_posemb(const float* __restrict__ in, const float* __restrict__ pos,
                         float* __restrict__ out) {
    int row = blockIdx.x * ROWS_PER_BLK + (threadIdx.x >> 5);
    if (row >= NTOK) return;
    int lane = threadIdx.x & 31;
    int t = row % L_TOK;
    float v[12]; float s2 = 0.f;
    #pragma unroll
    for (int j = 0; j < 12; j++) { v[j] = in[row * D_MODEL + lane + j * 32]; s2 += v[j] * v[j]; }
    s2 = warpSum(s2);
    float n = sqrtf(s2 + 1e-15f);
    n = fminf(fmaxf(n, 1e-8f), MAX_NORM);
    float coef = atanhf(fminf(SQRT_C * n, 0.95f)) / (SQRT_C * n);
    float su2 = 0.f;
    #pragma unroll
    for (int j = 0; j < 12; j++) {
        int e = lane + j * 32;
        v[j] = coef * v[j] + pos[t * D_MODEL + e];
        su2 += v[j] * v[j];
    }
    su2 = warpSum(su2);
    float nu = sqrtf(su2 + 1e-15f);
    nu = fminf(fmaxf(nu, 1e-8f), 5.0f);
    float ec = tanhf(SQRT_C * nu) / (SQRT_C * nu);
    float rn = sqrtf(ec * ec * su2 + 1e-15f);
    float scale = (rn > MAX_NORM) ? (MAX_NORM / rn) : 1.f;
    #pragma unroll
    for (int j = 0; j < 12; j++) out[row * D_MODEL + lane + j * 32] = ec * v[j] * scale;
}

// ---------------- depthwise causal conv + silu ------------------------------
__global__ void k_conv_silu(const float* __restrict__ xz, const float* __restrict__ cw,
                            const float* __restrict__ cb, float* __restrict__ u) {
    int idx = blockIdx.x * blockDim.x + threadIdx.x;
    if (idx >= NTOK * D_INNER) return;
    int d = idx % D_INNER, bt = idx / D_INNER;
    int b = bt / L_TOK, l = bt % L_TOK;
    float acc = cb[d];
    #pragma unroll
    for (int k = 0; k < D_CONV; k++) {
        int l2 = l + k - (D_CONV - 1);
        if (l2 >= 0) acc += cw[d * D_CONV + k] * xz[(b * L_TOK + l2) * (2 * D_INNER) + d];
    }
    u[idx] = acc * fsigmoid(acc);
}

// ---------------- dt projection + softplus ----------------------------------
__global__ void k_dtproj(const float* __restrict__ dbl, const float* __restrict__ dtw,
                         const float* __restrict__ dtb, float* __restrict__ dt) {
    int idx = blockIdx.x * blockDim.x + threadIdx.x;
    if (idx >= NTOK * D_INNER) return;
    int d = idx % D_INNER, bt = idx / D_INNER;
    float acc = dtb[d];
    #pragma unroll
    for (int r = 0; r < DT_RANK; r++)
        acc += dbl[bt * XPROJ_OUT + r] * dtw[d * DT_RANK + r];
    dt[idx] = (acc > 20.f) ? acc : log1pf(__expf(acc));
}

// ---------------- selective scan (+ Dp*u, * silu(z)) ------------------------
__global__ void k_scan(const float* __restrict__ dt, const float* __restrict__ u,
                       const float* __restrict__ dbl, const float* __restrict__ xz,
                       const float* __restrict__ A_log, const float* __restrict__ Dp,
                       float* __restrict__ y) {
    int gid = blockIdx.x * blockDim.x + threadIdx.x;
    int grp = gid >> 4, s = gid & 15;
    if (grp >= B_SZ * D_INNER) return;
    int b = grp / D_INNER, d = grp % D_INNER;
    float a = -expf(A_log[d * D_STATE + s]);
    float Dv = Dp[d];
    float h = 0.f;
    int base0 = b * L_TOK;
    for (int t = 0; t < L_TOK; t++) {
        int bt = base0 + t;
        float dtv = dt[bt * D_INNER + d];
        float uv  = u[bt * D_INNER + d];
        float Bv  = dbl[bt * XPROJ_OUT + DT_RANK + s];
        float Cv  = dbl[bt * XPROJ_OUT + DT_RANK + D_STATE + s];
        h = __expf(dtv * a) * h + dtv * Bv * uv;
        float p = h * Cv;
        p += __shfl_down_sync(0xffffffffu, p, 8, 16);
        p += __shfl_down_sync(0xffffffffu, p, 4, 16);
        p += __shfl_down_sync(0xffffffffu, p, 2, 16);
        p += __shfl_down_sync(0xffffffffu, p, 1, 16);
        if (s == 0) {
            float zv = xz[bt * (2 * D_INNER) + D_INNER + d];
            float yy = p + Dv * uv;
            yy *= zv * fsigmoid(zv);
            y[bt * D_INNER + d] = yy;
        }
    }
}

// ---------------- mean pool over tokens -------------------------------------
__global__ void k_pool(const float* __restrict__ in, float* __restrict__ out) {
    int b = blockIdx.x, e = threadIdx.x;
    float s = 0.f;
    for (int t = 0; t < L_TOK; t++) s += in[(b * L_TOK + t) * D_MODEL + e];
    out[b * D_MODEL + e] = s * (1.f / L_TOK);
}

// ---------------- hyperbolic distance classifier ----------------------------
__global__ void k_classifier(const float* __restrict__ pooled,
                             const float* __restrict__ protos,
                             float* __restrict__ out) {
    int warp = (blockIdx.x * blockDim.x + threadIdx.x) >> 5;
    int lane = threadIdx.x & 31;
    if (warp >= B_SZ * N_CLASSES) return;
    int b = warp / N_CLASSES, c = warp % N_CLASSES;
    float s_ab = 0.f, s_aa = 0.f, s_bb = 0.f;
    for (int e = lane; e < D_MODEL; e += 32) {
        float pa = pooled[b * D_MODEL + e];
        float pr = protos[c * D_MODEL + e];
        s_ab += pa * pr; s_aa += pa * pa; s_bb += pr * pr;
    }
    #pragma unroll
    for (int o = 16; o; o >>= 1) {
        s_ab += __shfl_down_sync(0xffffffffu, s_ab, o);
        s_aa += __shfl_down_sync(0xffffffffu, s_aa, o);
        s_bb += __shfl_down_sync(0xffffffffu, s_bb, o);
    }
    if (lane == 0) {
        float xy = -s_ab;          // a = -pooled
        float x2 = s_aa, y2 = s_bb;
        float alpha = 1.f + 2.f * C_CURV * xy + C_CURV * y2;
        float beta_ = 1.f - C_CURV * x2;
        float num2 = alpha * alpha * x2 + 2.f * alpha * beta_ * xy + beta_ * beta_ * y2;
        float den = fmaxf(1.f + 2.f * C_CURV * xy + C_CURV * C_CURV * x2 * y2, 1e-15f);
        float nrm = sqrtf(fmaxf(num2, 0.f) / (den * den) + 1e-15f);
        float dn = fminf(SQRT_C * nrm, 1.f - 1e-5f);
        out[b * N_CLASSES + c] = -(2.f / SQRT_C) * atanhf(dn);
    }
}

// ---------------- host orchestration ----------------------------------------
static void gemm(const float* A, const float* W, const float* bias, float* C,
                 int M, int N, int K) {
    dim3 grid((N + 63) / 64, (M + 127) / 128);
    if (bias) k_gemm_tf32<true><<<grid, 256>>>(A, W, bias, C, M, N, K);
    else      k_gemm_tf32<false><<<grid, 256>>>(A, W, nullptr, C, M, N, K);
}

#define ROW_GRID ((NTOK + ROWS_PER_BLK - 1) / ROWS_PER_BLK)

extern "C" void kernel_launch(void* const* d_in, const int* in_sizes, int n_in,
                              void* d_out, int out_size) {
    const float* x        = (const float*)d_in[0];
    const float* patch_w  = (const float*)d_in[1];
    const float* patch_b  = (const float*)d_in[2];
    const float* hyp_w    = (const float*)d_in[3];
    const float* hyp_b    = (const float*)d_in[4];
    const float* pe_gamma = (const float*)d_in[5];
    const float* pe_beta  = (const float*)d_in[6];
    const float* pos_emb  = (const float*)d_in[7];
    const float* in_proj  = (const float*)d_in[8];
    const float* conv_w   = (const float*)d_in[9];
    const float* conv_b   = (const float*)d_in[10];
    const float* x_proj   = (const float*)d_in[11];
    const float* dt_w     = (const float*)d_in[12];
    const float* dt_b     = (const float*)d_in[13];
    const float* A_log    = (const float*)d_in[14];
    const float* Dp       = (const float*)d_in[15];
    const float* out_proj = (const float*)d_in[16];
    const float* gamma    = (const float*)d_in[17];
    const float* beta     = (const float*)d_in[18];
    const float* gamma_f  = (const float*)d_in[19];
    const float* beta_f   = (const float*)d_in[20];
    const float* protos   = (const float*)d_in[21];
    float* out = (float*)d_out;

    float *patches, *hidden, *resid, *hn, *tmp, *xz, *u, *dbl, *dtb_, *yb, *pool;
    cudaGetSymbolAddress((void**)&patches, g_patches);
    cudaGetSymbolAddress((void**)&hidden,  g_hidden);
    cudaGetSymbolAddress((void**)&resid,   g_resid);
    cudaGetSymbolAddress((void**)&hn,      g_hn);
    cudaGetSymbolAddress((void**)&tmp,     g_tmp);
    cudaGetSymbolAddress((void**)&xz,      g_xz);
    cudaGetSymbolAddress((void**)&u,       g_u);
    cudaGetSymbolAddress((void**)&dbl,     g_dbl);
    cudaGetSymbolAddress((void**)&dtb_,    g_dt);
    cudaGetSymbolAddress((void**)&yb,      g_y);
    cudaGetSymbolAddress((void**)&pool,    g_pool);

    // patch embed -> tokens
    k_im2col<<<(NTOK * 768 + 255) / 256, 256>>>(x);
    gemm(patches, patch_w, patch_b, hidden, NTOK, D_MODEL, 768);
    // hyperbolic embedding
    k_expmap_rows<<<ROW_GRID, 256>>>(hidden, hidden, NTOK);
    gemm(hidden, hyp_w, nullptr, tmp, NTOK, D_MODEL, D_MODEL);
    k_mobius<<<ROW_GRID, 256>>>(hidden, tmp, hyp_b, hidden);
    k_resid_hyp_ln<<<ROW_GRID, 256>>>(hidden, tmp, pe_gamma, pe_beta, hidden, 0);
    k_posemb<<<ROW_GRID, 256>>>(hidden, pos_emb, hidden);

    for (int i = 0; i < DEPTH; i++) {
        k_resid_hyp_ln<<<ROW_GRID, 256>>>(hidden, resid,
                                          gamma + i * D_MODEL, beta + i * D_MODEL,
                                          hn, i > 0);
        gemm(hn, in_proj + (size_t)i * 2 * D_INNER * D_MODEL, nullptr, xz,
             NTOK, 2 * D_INNER, D_MODEL);
        k_conv_silu<<<(NTOK * D_INNER + 255) / 256, 256>>>(
            xz, conv_w + i * D_INNER * D_CONV, conv_b + i * D_INNER, u);
        gemm(u, x_proj + (size_t)i * XPROJ_OUT * D_INNER, nullptr, dbl,
             NTOK, XPROJ_OUT, D_INNER);
        k_dtproj<<<(NTOK * D_INNER + 255) / 256, 256>>>(
            dbl, dt_w + (size_t)i * D_INNER * DT_RANK, dt_b + i * D_INNER, dtb_);
        k_scan<<<(B_SZ * D_INNER * 16 + 255) / 256, 256>>>(
            dtb_, u, dbl, xz, A_log + (size_t)i * D_INNER * D_STATE, Dp + i * D_INNER, yb);
        gemm(yb, out_proj + (size_t)i * D_MODEL * D_INNER, nullptr, hidden,
             NTOK, D_MODEL, D_INNER);
    }

    // final residual + LN + pool + classify
    k_resid_hyp_ln<<<ROW_GRID, 256>>>(hidden, resid, gamma_f, beta_f, hn, 1);
    k_logmap_rows<<<ROW_GRID, 256>>>(hn, tmp, NTOK);
    k_pool<<<B_SZ, D_MODEL>>>(tmp, pool);
    k_expmap_rows<<<(B_SZ + ROWS_PER_BLK - 1) / ROWS_PER_BLK, 256>>>(pool, pool, B_SZ);
    k_classifier<<<(B_SZ * N_CLASSES * 32 + 255) / 256, 256>>>(pool, protos, out);
}